// round 2
// baseline (speedup 1.0000x reference)
#include <cuda_runtime.h>
#include <math.h>

// ---------------------------------------------------------------------------
// Problem constants
// ---------------------------------------------------------------------------
#define BATCH    32
#define HRES     56
#define CDIM     384
#define NHEADS   12
#define HDIM     32
#define WSZ      7
#define NTOK     49           // tokens per window
#define SHIFT_   3
#define NWIN_IMG 64           // windows per image (8x8)
#define NWIN_TOT 2048         // BATCH * NWIN_IMG
#define LTOK     3136         // HRES*HRES
#define MROWS    100352       // BATCH * LTOK  (= NWIN_TOT * NTOK)
#define MLPH     1536
#define SCALE_QK 0.17677669529663687f   // 32^-0.5

// ---------------------------------------------------------------------------
// Scratch (device globals; no allocation allowed)
// ---------------------------------------------------------------------------
__device__ float g_xw  [(size_t)MROWS * CDIM];   // LN1+windowed  (reused as LN2 output)
__device__ float g_qkv [(size_t)MROWS * 3 * CDIM];
__device__ float g_attn[(size_t)MROWS * CDIM];
__device__ float g_x2  [(size_t)MROWS * CDIM];   // shortcut + attn branch
__device__ float g_h1  [(size_t)MROWS * MLPH];

// ---------------------------------------------------------------------------
// Window-row <-> image-location map. Because SHIFT roll (-3) on the forward
// path and (+3) on the reverse path, BOTH directions use the same formula:
//   window-row wr  <->  image row (b, l) with l = ((hs+3)%56)*56 + (ws+3)%56
// ---------------------------------------------------------------------------
__device__ __forceinline__ void map_row(int wr, int& b, int& l) {
    b = wr / LTOK;
    int rem  = wr - b * LTOK;
    int win  = rem / NTOK;
    int tok  = rem - win * NTOK;
    int wrow = win >> 3, wcol = win & 7;
    int i = tok / WSZ, j = tok - i * WSZ;
    int hs = wrow * WSZ + i + SHIFT_; if (hs >= HRES) hs -= HRES;
    int ws = wcol * WSZ + j + SHIFT_; if (ws >= HRES) ws -= HRES;
    l = hs * HRES + ws;
}

// ---------------------------------------------------------------------------
// LayerNorm kernels.
//   GATHER = true : read original x at shifted/windowed location -> g_xw (LN1)
//   GATHER = false: read g_x2 row directly                      -> g_xw (LN2)
// One block (128 threads) per row of 384.
// ---------------------------------------------------------------------------
template <bool GATHER>
__global__ __launch_bounds__(128) void ln_kernel(const float* __restrict__ xin,
                                                 const float* __restrict__ w,
                                                 const float* __restrict__ bprm) {
    int row = blockIdx.x;
    int tid = threadIdx.x;

    const float* src;
    if (GATHER) {
        int b, l; map_row(row, b, l);
        src = xin + ((size_t)b * LTOK + l) * CDIM;
    } else {
        src = g_x2 + (size_t)row * CDIM;
    }

    float v0 = src[tid], v1 = src[tid + 128], v2 = src[tid + 256];
    float s  = v0 + v1 + v2;
    float s2 = v0 * v0 + v1 * v1 + v2 * v2;

    #pragma unroll
    for (int o = 16; o > 0; o >>= 1) {
        s  += __shfl_down_sync(0xffffffffu, s,  o);
        s2 += __shfl_down_sync(0xffffffffu, s2, o);
    }
    __shared__ float ws1[4], ws2[4];
    int lane = tid & 31, wid = tid >> 5;
    if (lane == 0) { ws1[wid] = s; ws2[wid] = s2; }
    __syncthreads();
    s  = ws1[0] + ws1[1] + ws1[2] + ws1[3];
    s2 = ws2[0] + ws2[1] + ws2[2] + ws2[3];

    float mu   = s * (1.0f / CDIM);
    float var  = s2 * (1.0f / CDIM) - mu * mu;
    float rstd = rsqrtf(var + 1e-5f);

    float* dst = g_xw + (size_t)row * CDIM;
    dst[tid]       = (v0 - mu) * rstd * w[tid]       + bprm[tid];
    dst[tid + 128] = (v1 - mu) * rstd * w[tid + 128] + bprm[tid + 128];
    dst[tid + 256] = (v2 - mu) * rstd * w[tid + 256] + bprm[tid + 256];
}

// ---------------------------------------------------------------------------
// SGEMM: C[m,n] = sum_k A[m,k] * W[n,k]  (+ mode-specific epilogue)
// 128x128 tile, BK=16, 256 threads, 8x8 microtile in 4 quadrants.
// Double-buffered smem + register-staged global prefetch:
//   - next K-tile's global loads issue BEFORE the current compute loop
//   - one __syncthreads per K-step instead of two
//   MODE 0: A=g_xw,  out=g_qkv               (+bias)                 N=1152 K=384
//   MODE 1: A=g_attn,out=g_x2 (scattered)    (+bias +resid(x))       N=384  K=384
//   MODE 2: A=g_xw,  out=g_h1                (+bias, exact GELU)     N=1536 K=384
//   MODE 3: A=g_h1,  out=d_out               (+bias +g_x2 residual)  N=384  K=1536
// All of M,N divisible by 128 and K by 16 -> no bounds checks.
// ---------------------------------------------------------------------------
__device__ __forceinline__ float gelu_exact(float v) {
    return 0.5f * v * (1.0f + erff(v * 0.70710678118654752f));
}

template <int MODE, int K, int N>
__global__ __launch_bounds__(256) void gemm_kernel(const float* __restrict__ Wm,
                                                   const float* __restrict__ bias,
                                                   const float* __restrict__ resid,
                                                   float* __restrict__ outp) {
    const float* A = (MODE == 0) ? g_xw
                   : (MODE == 1) ? g_attn
                   : (MODE == 2) ? g_xw
                   :               g_h1;

    __shared__ float As[2][16][128];
    __shared__ float Bs[2][16][128];

    int tid = threadIdx.x;
    int tx = tid & 15, ty = tid >> 4;
    int rowBase = blockIdx.y * 128;
    int colBase = blockIdx.x * 128;

    // Per-thread staging coordinates: 2 float4 of A, 2 of B per K-tile.
    int ldR[2], ldC[2];
    #pragma unroll
    for (int j = 0; j < 2; ++j) {
        int idx = tid * 2 + j;
        ldR[j] = idx >> 2;            // 0..127
        ldC[j] = (idx & 3) * 4;       // 0,4,8,12
    }

    float acc[8][8];
    #pragma unroll
    for (int i = 0; i < 8; ++i)
        #pragma unroll
        for (int j = 0; j < 8; ++j) acc[i][j] = 0.0f;

    // Prologue: fill buffer 0 with K-tile 0.
    #pragma unroll
    for (int j = 0; j < 2; ++j) {
        float4 av = *(const float4*)(A  + (size_t)(rowBase + ldR[j]) * K + ldC[j]);
        As[0][ldC[j] + 0][ldR[j]] = av.x; As[0][ldC[j] + 1][ldR[j]] = av.y;
        As[0][ldC[j] + 2][ldR[j]] = av.z; As[0][ldC[j] + 3][ldR[j]] = av.w;
        float4 wv = *(const float4*)(Wm + (size_t)(colBase + ldR[j]) * K + ldC[j]);
        Bs[0][ldC[j] + 0][ldR[j]] = wv.x; Bs[0][ldC[j] + 1][ldR[j]] = wv.y;
        Bs[0][ldC[j] + 2][ldR[j]] = wv.z; Bs[0][ldC[j] + 3][ldR[j]] = wv.w;
    }
    __syncthreads();

    int buf = 0;
    for (int k0 = 0; k0 < K; k0 += 16) {
        float4 avr[2], wvr[2];
        const bool hasNext = (k0 + 16 < K);
        if (hasNext) {
            #pragma unroll
            for (int j = 0; j < 2; ++j) {
                avr[j] = *(const float4*)(A  + (size_t)(rowBase + ldR[j]) * K + k0 + 16 + ldC[j]);
                wvr[j] = *(const float4*)(Wm + (size_t)(colBase + ldR[j]) * K + k0 + 16 + ldC[j]);
            }
        }

        #pragma unroll
        for (int kk = 0; kk < 16; ++kk) {
            float a[8], b[8];
            *(float4*)&a[0] = *(const float4*)&As[buf][kk][ty * 4];
            *(float4*)&a[4] = *(const float4*)&As[buf][kk][64 + ty * 4];
            *(float4*)&b[0] = *(const float4*)&Bs[buf][kk][tx * 4];
            *(float4*)&b[4] = *(const float4*)&Bs[buf][kk][64 + tx * 4];
            #pragma unroll
            for (int i = 0; i < 8; ++i)
                #pragma unroll
                for (int j = 0; j < 8; ++j)
                    acc[i][j] += a[i] * b[j];
        }

        if (hasNext) {
            int nb = buf ^ 1;
            #pragma unroll
            for (int j = 0; j < 2; ++j) {
                As[nb][ldC[j] + 0][ldR[j]] = avr[j].x; As[nb][ldC[j] + 1][ldR[j]] = avr[j].y;
                As[nb][ldC[j] + 2][ldR[j]] = avr[j].z; As[nb][ldC[j] + 3][ldR[j]] = avr[j].w;
                Bs[nb][ldC[j] + 0][ldR[j]] = wvr[j].x; Bs[nb][ldC[j] + 1][ldR[j]] = wvr[j].y;
                Bs[nb][ldC[j] + 2][ldR[j]] = wvr[j].z; Bs[nb][ldC[j] + 3][ldR[j]] = wvr[j].w;
            }
            __syncthreads();
            buf = nb;
        }
    }

    #pragma unroll
    for (int i = 0; i < 8; ++i) {
        int r = rowBase + ((i < 4) ? (ty * 4 + i) : (64 + ty * 4 + i - 4));
        size_t scatterOff = 0;
        if (MODE == 1) {
            int b, l; map_row(r, b, l);
            scatterOff = ((size_t)b * LTOK + l) * CDIM;
        }
        #pragma unroll
        for (int j = 0; j < 8; ++j) {
            int c = colBase + ((j < 4) ? (tx * 4 + j) : (64 + tx * 4 + j - 4));
            float v = acc[i][j] + bias[c];
            if (MODE == 0) {
                g_qkv[(size_t)r * N + c] = v;
            } else if (MODE == 1) {
                g_x2[scatterOff + c] = resid[scatterOff + c] + v;
            } else if (MODE == 2) {
                g_h1[(size_t)r * N + c] = gelu_exact(v);
            } else {
                outp[(size_t)r * N + c] = g_x2[(size_t)r * N + c] + v;
            }
        }
    }
}

// ---------------------------------------------------------------------------
// Windowed attention: one CTA per (head, window).
// qkv column layout (from reference chunk order): [v | q | k], each C wide,
// head h occupies cols h*32 .. h*32+31 within its chunk.
// ---------------------------------------------------------------------------
__global__ __launch_bounds__(256) void attn_kernel(const float* __restrict__ rb) {
    int head = blockIdx.x;
    int win  = blockIdx.y;
    int tid  = threadIdx.x;

    __shared__ float sq[NTOK * HDIM];
    __shared__ float sk[NTOK * HDIM];
    __shared__ float sv[NTOK * HDIM];
    __shared__ float ss[NTOK * NTOK];
    __shared__ float sb[169];           // (2*7-1)^2 rel-bias for this head
    __shared__ int   slab[NTOK];        // shift-mask labels

    size_t base = (size_t)win * NTOK * (3 * CDIM) + head * HDIM;
    for (int idx = tid; idx < NTOK * HDIM; idx += 256) {
        int n = idx >> 5, d = idx & 31;
        size_t p = base + (size_t)n * (3 * CDIM) + d;
        sv[idx] = g_qkv[p];              // chunk 0 = v
        sq[idx] = g_qkv[p + CDIM];       // chunk 1 = q
        sk[idx] = g_qkv[p + 2 * CDIM];   // chunk 2 = k
    }
    if (tid < 169) sb[tid] = rb[head * 169 + tid];
    if (tid < NTOK) {
        int w_in = win & (NWIN_IMG - 1);
        int wrow = w_in >> 3, wcol = w_in & 7;
        int h = wrow * WSZ + tid / WSZ;
        int w = wcol * WSZ + tid % WSZ;
        int lh = (h < HRES - WSZ) ? 0 : ((h < HRES - SHIFT_) ? 1 : 2);
        int lw = (w < HRES - WSZ) ? 0 : ((w < HRES - SHIFT_) ? 1 : 2);
        slab[tid] = lh * 3 + lw;
    }
    __syncthreads();

    // scores + rel bias + shift mask
    for (int e = tid; e < NTOK * NTOK; e += 256) {
        int n = e / NTOK, m = e - n * NTOK;
        float dot = 0.0f;
        #pragma unroll
        for (int t = 0; t < HDIM; ++t) dot += sq[n * HDIM + t] * sk[m * HDIM + t];
        int in = n / WSZ, jn = n % WSZ, im = m / WSZ, jm = m % WSZ;
        int rid = (im - in + WSZ - 1) * (2 * WSZ - 1) + (jm - jn + WSZ - 1);
        float msk = (slab[n] != slab[m]) ? -100.0f : 0.0f;
        ss[e] = dot * SCALE_QK + sb[rid] + msk;
    }
    __syncthreads();

    // softmax rows (49 rows; thread-per-row is fine at this size)
    for (int r = tid; r < NTOK; r += 256) {
        float mx = -1e30f;
        for (int m = 0; m < NTOK; ++m) mx = fmaxf(mx, ss[r * NTOK + m]);
        float sum = 0.0f;
        for (int m = 0; m < NTOK; ++m) {
            float e = expf(ss[r * NTOK + m] - mx);
            ss[r * NTOK + m] = e;
            sum += e;
        }
        float inv = 1.0f / sum;
        for (int m = 0; m < NTOK; ++m) ss[r * NTOK + m] *= inv;
    }
    __syncthreads();

    // O = P @ V   -> layout (win, tok, head*32+d)
    for (int e = tid; e < NTOK * HDIM; e += 256) {
        int n = e >> 5, d = e & 31;
        float o = 0.0f;
        #pragma unroll
        for (int m = 0; m < NTOK; ++m) o += ss[n * NTOK + m] * sv[m * HDIM + d];
        g_attn[((size_t)win * NTOK + n) * CDIM + head * HDIM + d] = o;
    }
}

// ---------------------------------------------------------------------------
// Launcher — pure kernel launches, graph-capturable, allocation-free.
// Input order: x, norm1_w, norm1_b, qkv_w, qkv_b, rb, proj_w, proj_b,
//              norm2_w, norm2_b, fc1_w, fc1_b, fc2_w, fc2_b
// ---------------------------------------------------------------------------
extern "C" void kernel_launch(void* const* d_in, const int* in_sizes, int n_in,
                              void* d_out, int out_size) {
    const float* x      = (const float*)d_in[0];
    const float* n1w    = (const float*)d_in[1];
    const float* n1b    = (const float*)d_in[2];
    const float* qkvw   = (const float*)d_in[3];
    const float* qkvb   = (const float*)d_in[4];
    const float* rb     = (const float*)d_in[5];
    const float* projw  = (const float*)d_in[6];
    const float* projb  = (const float*)d_in[7];
    const float* n2w    = (const float*)d_in[8];
    const float* n2b    = (const float*)d_in[9];
    const float* fc1w   = (const float*)d_in[10];
    const float* fc1b   = (const float*)d_in[11];
    const float* fc2w   = (const float*)d_in[12];
    const float* fc2b   = (const float*)d_in[13];
    float*       out    = (float*)d_out;

    // 1. LN1 + shift + window partition
    ln_kernel<true><<<MROWS, 128>>>(x, n1w, n1b);

    // 2. QKV projection (M=100352, N=1152, K=384)
    gemm_kernel<0, 384, 1152><<<dim3(1152 / 128, MROWS / 128), 256>>>(qkvw, qkvb, nullptr, nullptr);

    // 3. Windowed attention
    attn_kernel<<<dim3(NHEADS, NWIN_TOT), 256>>>(rb);

    // 4. proj + window reverse + unshift + residual  -> g_x2
    gemm_kernel<1, 384, 384><<<dim3(384 / 128, MROWS / 128), 256>>>(projw, projb, x, nullptr);

    // 5. LN2 (image order) -> g_xw
    ln_kernel<false><<<MROWS, 128>>>(nullptr, n2w, n2b);

    // 6. FC1 + exact GELU  (N=1536, K=384)
    gemm_kernel<2, 384, 1536><<<dim3(1536 / 128, MROWS / 128), 256>>>(fc1w, fc1b, nullptr, nullptr);

    // 7. FC2 + residual -> d_out  (N=384, K=1536)
    gemm_kernel<3, 1536, 384><<<dim3(384 / 128, MROWS / 128), 256>>>(fc2w, fc2b, nullptr, out);
}

// round 5
// speedup vs baseline: 1.4797x; 1.4797x over previous
#include <cuda_runtime.h>
#include <math.h>
#include <stdint.h>

// ---------------------------------------------------------------------------
// Problem constants
// ---------------------------------------------------------------------------
#define BATCH    32
#define HRES     56
#define CDIM     384
#define NHEADS   12
#define HDIM     32
#define WSZ      7
#define NTOK     49
#define SHIFT_   3
#define NWIN_IMG 64
#define NWIN_TOT 2048
#define LTOK     3136
#define MROWS    100352
#define MLPH     1536
#define SCALE_QK 0.17677669529663687f

// ---------------------------------------------------------------------------
// Scratch (device globals; no allocation allowed)
// ---------------------------------------------------------------------------
__device__ float g_xw  [(size_t)MROWS * CDIM];
__device__ float g_qkv [(size_t)MROWS * 3 * CDIM];
__device__ float g_attn[(size_t)MROWS * CDIM];
__device__ float g_x2  [(size_t)MROWS * CDIM];
__device__ float g_h1  [(size_t)MROWS * MLPH];

// ---------------------------------------------------------------------------
__device__ __forceinline__ void map_row(int wr, int& b, int& l) {
    b = wr / LTOK;
    int rem  = wr - b * LTOK;
    int win  = rem / NTOK;
    int tok  = rem - win * NTOK;
    int wrow = win >> 3, wcol = win & 7;
    int i = tok / WSZ, j = tok - i * WSZ;
    int hs = wrow * WSZ + i + SHIFT_; if (hs >= HRES) hs -= HRES;
    int ws = wcol * WSZ + j + SHIFT_; if (ws >= HRES) ws -= HRES;
    l = hs * HRES + ws;
}

// ---------------------------------------------------------------------------
// LayerNorm (unchanged from passing baseline)
// ---------------------------------------------------------------------------
template <bool GATHER>
__global__ __launch_bounds__(128) void ln_kernel(const float* __restrict__ xin,
                                                 const float* __restrict__ w,
                                                 const float* __restrict__ bprm) {
    int row = blockIdx.x;
    int tid = threadIdx.x;

    const float* src;
    if (GATHER) {
        int b, l; map_row(row, b, l);
        src = xin + ((size_t)b * LTOK + l) * CDIM;
    } else {
        src = g_x2 + (size_t)row * CDIM;
    }

    float v0 = src[tid], v1 = src[tid + 128], v2 = src[tid + 256];
    float s  = v0 + v1 + v2;
    float s2 = v0 * v0 + v1 * v1 + v2 * v2;

    #pragma unroll
    for (int o = 16; o > 0; o >>= 1) {
        s  += __shfl_down_sync(0xffffffffu, s,  o);
        s2 += __shfl_down_sync(0xffffffffu, s2, o);
    }
    __shared__ float ws1[4], ws2[4];
    int lane = tid & 31, wid = tid >> 5;
    if (lane == 0) { ws1[wid] = s; ws2[wid] = s2; }
    __syncthreads();
    s  = ws1[0] + ws1[1] + ws1[2] + ws1[3];
    s2 = ws2[0] + ws2[1] + ws2[2] + ws2[3];

    float mu   = s * (1.0f / CDIM);
    float var  = s2 * (1.0f / CDIM) - mu * mu;
    float rstd = rsqrtf(var + 1e-5f);

    float* dst = g_xw + (size_t)row * CDIM;
    dst[tid]       = (v0 - mu) * rstd * w[tid]       + bprm[tid];
    dst[tid + 128] = (v1 - mu) * rstd * w[tid + 128] + bprm[tid + 128];
    dst[tid + 256] = (v2 - mu) * rstd * w[tid + 256] + bprm[tid + 256];
}

// ---------------------------------------------------------------------------
// TF32 tensor-core GEMM: C[m,n] = sum_k A[m,k] * W[n,k]  (+ fused epilogue)
// Block 128x128, BK=16 double-buffered, 256 threads = 8 warps (4m x 2n),
// warp tile 32x64 = (2 x m16) x (8 x n8), mma.sync.m16n8k8 tf32, fp32 accum.
//   MODE 0: out=g_qkv  (+bias)               MODE 1: out=g_x2 scatter (+bias+resid)
//   MODE 2: out=g_h1   (+bias, GELU)         MODE 3: out=outp (+bias+g_x2)
// ---------------------------------------------------------------------------
__device__ __forceinline__ float gelu_exact(float v) {
    return 0.5f * v * (1.0f + erff(v * 0.70710678118654752f));
}

__device__ __forceinline__ float f2tf(float f) {
    uint32_t u;
    asm("cvt.rna.tf32.f32 %0, %1;" : "=r"(u) : "f"(f));
    return __uint_as_float(u);
}

__device__ __forceinline__ void mma_tf32(float* d, const uint32_t* a, const uint32_t* b) {
    asm volatile(
        "mma.sync.aligned.m16n8k8.row.col.f32.tf32.tf32.f32 "
        "{%0,%1,%2,%3}, {%4,%5,%6,%7}, {%8,%9}, {%0,%1,%2,%3};\n"
        : "+f"(d[0]), "+f"(d[1]), "+f"(d[2]), "+f"(d[3])
        : "r"(a[0]), "r"(a[1]), "r"(a[2]), "r"(a[3]), "r"(b[0]), "r"(b[1]));
}

#define SPAD 132   // 128 + 4 padding: fragment LDS <=2-way conflicts

template <int MODE, int K, int N>
__global__ __launch_bounds__(256, 2) void gemm_kernel(const float* __restrict__ Wm,
                                                      const float* __restrict__ bias,
                                                      const float* __restrict__ resid,
                                                      float* __restrict__ outp) {
    const float* A = (MODE == 0) ? g_xw
                   : (MODE == 1) ? g_attn
                   : (MODE == 2) ? g_xw
                   :               g_h1;

    __shared__ float As[2][16][SPAD];
    __shared__ float Bs[2][16][SPAD];

    const int tid   = threadIdx.x;
    const int lane  = tid & 31;
    const int warp  = tid >> 5;
    const int mwarp = warp >> 1;      // 0..3
    const int nwarp = warp & 1;       // 0..1
    const int qrow  = lane >> 2;      // 0..7
    const int qk    = lane & 3;       // 0..3

    const int rowBase = blockIdx.y * 128;
    const int colBase = blockIdx.x * 128;

    // global->smem staging coords: 2 float4 of A and of W per thread per tile
    int ldR[2], ldC[2];
    #pragma unroll
    for (int j = 0; j < 2; ++j) {
        int idx = tid * 2 + j;
        ldR[j] = idx >> 2;
        ldC[j] = (idx & 3) * 4;
    }

    float acc[2][8][4];
    #pragma unroll
    for (int mt = 0; mt < 2; ++mt)
        #pragma unroll
        for (int nt = 0; nt < 8; ++nt)
            #pragma unroll
            for (int e = 0; e < 4; ++e) acc[mt][nt][e] = 0.0f;

    // Prologue: K-tile 0 into buffer 0 (tf32-rounded)
    #pragma unroll
    for (int j = 0; j < 2; ++j) {
        float4 av = *(const float4*)(A  + (size_t)(rowBase + ldR[j]) * K + ldC[j]);
        As[0][ldC[j] + 0][ldR[j]] = f2tf(av.x); As[0][ldC[j] + 1][ldR[j]] = f2tf(av.y);
        As[0][ldC[j] + 2][ldR[j]] = f2tf(av.z); As[0][ldC[j] + 3][ldR[j]] = f2tf(av.w);
        float4 wv = *(const float4*)(Wm + (size_t)(colBase + ldR[j]) * K + ldC[j]);
        Bs[0][ldC[j] + 0][ldR[j]] = f2tf(wv.x); Bs[0][ldC[j] + 1][ldR[j]] = f2tf(wv.y);
        Bs[0][ldC[j] + 2][ldR[j]] = f2tf(wv.z); Bs[0][ldC[j] + 3][ldR[j]] = f2tf(wv.w);
    }
    __syncthreads();

    int buf = 0;
    for (int k0 = 0; k0 < K; k0 += 16) {
        float4 avr[2], wvr[2];
        const bool hasNext = (k0 + 16 < K);
        if (hasNext) {
            #pragma unroll
            for (int j = 0; j < 2; ++j) {
                avr[j] = *(const float4*)(A  + (size_t)(rowBase + ldR[j]) * K + k0 + 16 + ldC[j]);
                wvr[j] = *(const float4*)(Wm + (size_t)(colBase + ldR[j]) * K + k0 + 16 + ldC[j]);
            }
        }

        #pragma unroll
        for (int k8 = 0; k8 < 16; k8 += 8) {
            uint32_t afrag[2][4], bfrag[8][2];
            #pragma unroll
            for (int mt = 0; mt < 2; ++mt) {
                int moff = mwarp * 32 + mt * 16;
                afrag[mt][0] = __float_as_uint(As[buf][k8 + qk    ][moff + qrow    ]);
                afrag[mt][1] = __float_as_uint(As[buf][k8 + qk    ][moff + qrow + 8]);
                afrag[mt][2] = __float_as_uint(As[buf][k8 + qk + 4][moff + qrow    ]);
                afrag[mt][3] = __float_as_uint(As[buf][k8 + qk + 4][moff + qrow + 8]);
            }
            #pragma unroll
            for (int nt = 0; nt < 8; ++nt) {
                int noff = nwarp * 64 + nt * 8;
                bfrag[nt][0] = __float_as_uint(Bs[buf][k8 + qk    ][noff + qrow]);
                bfrag[nt][1] = __float_as_uint(Bs[buf][k8 + qk + 4][noff + qrow]);
            }
            #pragma unroll
            for (int mt = 0; mt < 2; ++mt)
                #pragma unroll
                for (int nt = 0; nt < 8; ++nt)
                    mma_tf32(acc[mt][nt], afrag[mt], bfrag[nt]);
        }

        if (hasNext) {
            int nb = buf ^ 1;
            #pragma unroll
            for (int j = 0; j < 2; ++j) {
                As[nb][ldC[j] + 0][ldR[j]] = f2tf(avr[j].x); As[nb][ldC[j] + 1][ldR[j]] = f2tf(avr[j].y);
                As[nb][ldC[j] + 2][ldR[j]] = f2tf(avr[j].z); As[nb][ldC[j] + 3][ldR[j]] = f2tf(avr[j].w);
                Bs[nb][ldC[j] + 0][ldR[j]] = f2tf(wvr[j].x); Bs[nb][ldC[j] + 1][ldR[j]] = f2tf(wvr[j].y);
                Bs[nb][ldC[j] + 2][ldR[j]] = f2tf(wvr[j].z); Bs[nb][ldC[j] + 3][ldR[j]] = f2tf(wvr[j].w);
            }
            __syncthreads();
            buf = nb;
        }
    }

    // Epilogue: thread owns rows {base, base+8} x 2 m-tiles, col pairs per n-tile
    #pragma unroll
    for (int mt = 0; mt < 2; ++mt) {
        #pragma unroll
        for (int rh = 0; rh < 2; ++rh) {
            int r = rowBase + mwarp * 32 + mt * 16 + qrow + rh * 8;
            size_t scatterOff = 0;
            if (MODE == 1) {
                int b, l; map_row(r, b, l);
                scatterOff = ((size_t)b * LTOK + l) * CDIM;
            }
            #pragma unroll
            for (int nt = 0; nt < 8; ++nt) {
                int c = colBase + nwarp * 64 + nt * 8 + 2 * qk;
                float v0 = acc[mt][nt][rh * 2 + 0] + bias[c];
                float v1 = acc[mt][nt][rh * 2 + 1] + bias[c + 1];
                if (MODE == 0) {
                    *(float2*)&g_qkv[(size_t)r * N + c] = make_float2(v0, v1);
                } else if (MODE == 1) {
                    float2 rs = *(const float2*)&resid[scatterOff + c];
                    *(float2*)&g_x2[scatterOff + c] = make_float2(rs.x + v0, rs.y + v1);
                } else if (MODE == 2) {
                    *(float2*)&g_h1[(size_t)r * N + c] =
                        make_float2(gelu_exact(v0), gelu_exact(v1));
                } else {
                    float2 rs = *(const float2*)&g_x2[(size_t)r * N + c];
                    *(float2*)&outp[(size_t)r * N + c] = make_float2(rs.x + v0, rs.y + v1);
                }
            }
        }
    }
}

// ---------------------------------------------------------------------------
// Windowed attention (unchanged from passing baseline)
// ---------------------------------------------------------------------------
__global__ __launch_bounds__(256) void attn_kernel(const float* __restrict__ rb) {
    int head = blockIdx.x;
    int win  = blockIdx.y;
    int tid  = threadIdx.x;

    __shared__ float sq[NTOK * HDIM];
    __shared__ float sk[NTOK * HDIM];
    __shared__ float sv[NTOK * HDIM];
    __shared__ float ss[NTOK * NTOK];
    __shared__ float sb[169];
    __shared__ int   slab[NTOK];

    size_t base = (size_t)win * NTOK * (3 * CDIM) + head * HDIM;
    for (int idx = tid; idx < NTOK * HDIM; idx += 256) {
        int n = idx >> 5, d = idx & 31;
        size_t p = base + (size_t)n * (3 * CDIM) + d;
        sv[idx] = g_qkv[p];
        sq[idx] = g_qkv[p + CDIM];
        sk[idx] = g_qkv[p + 2 * CDIM];
    }
    if (tid < 169) sb[tid] = rb[head * 169 + tid];
    if (tid < NTOK) {
        int w_in = win & (NWIN_IMG - 1);
        int wrow = w_in >> 3, wcol = w_in & 7;
        int h = wrow * WSZ + tid / WSZ;
        int w = wcol * WSZ + tid % WSZ;
        int lh = (h < HRES - WSZ) ? 0 : ((h < HRES - SHIFT_) ? 1 : 2);
        int lw = (w < HRES - WSZ) ? 0 : ((w < HRES - SHIFT_) ? 1 : 2);
        slab[tid] = lh * 3 + lw;
    }
    __syncthreads();

    for (int e = tid; e < NTOK * NTOK; e += 256) {
        int n = e / NTOK, m = e - n * NTOK;
        float dot = 0.0f;
        #pragma unroll
        for (int t = 0; t < HDIM; ++t) dot += sq[n * HDIM + t] * sk[m * HDIM + t];
        int in = n / WSZ, jn = n % WSZ, im = m / WSZ, jm = m % WSZ;
        int rid = (im - in + WSZ - 1) * (2 * WSZ - 1) + (jm - jn + WSZ - 1);
        float msk = (slab[n] != slab[m]) ? -100.0f : 0.0f;
        ss[e] = dot * SCALE_QK + sb[rid] + msk;
    }
    __syncthreads();

    for (int r = tid; r < NTOK; r += 256) {
        float mx = -1e30f;
        for (int m = 0; m < NTOK; ++m) mx = fmaxf(mx, ss[r * NTOK + m]);
        float sum = 0.0f;
        for (int m = 0; m < NTOK; ++m) {
            float e = expf(ss[r * NTOK + m] - mx);
            ss[r * NTOK + m] = e;
            sum += e;
        }
        float inv = 1.0f / sum;
        for (int m = 0; m < NTOK; ++m) ss[r * NTOK + m] *= inv;
    }
    __syncthreads();

    for (int e = tid; e < NTOK * HDIM; e += 256) {
        int n = e >> 5, d = e & 31;
        float o = 0.0f;
        #pragma unroll
        for (int m = 0; m < NTOK; ++m) o += ss[n * NTOK + m] * sv[m * HDIM + d];
        g_attn[((size_t)win * NTOK + n) * CDIM + head * HDIM + d] = o;
    }
}

// ---------------------------------------------------------------------------
extern "C" void kernel_launch(void* const* d_in, const int* in_sizes, int n_in,
                              void* d_out, int out_size) {
    const float* x      = (const float*)d_in[0];
    const float* n1w    = (const float*)d_in[1];
    const float* n1b    = (const float*)d_in[2];
    const float* qkvw   = (const float*)d_in[3];
    const float* qkvb   = (const float*)d_in[4];
    const float* rb     = (const float*)d_in[5];
    const float* projw  = (const float*)d_in[6];
    const float* projb  = (const float*)d_in[7];
    const float* n2w    = (const float*)d_in[8];
    const float* n2b    = (const float*)d_in[9];
    const float* fc1w   = (const float*)d_in[10];
    const float* fc1b   = (const float*)d_in[11];
    const float* fc2w   = (const float*)d_in[12];
    const float* fc2b   = (const float*)d_in[13];
    float*       out    = (float*)d_out;

    ln_kernel<true><<<MROWS, 128>>>(x, n1w, n1b);

    gemm_kernel<0, 384, 1152><<<dim3(1152 / 128, MROWS / 128), 256>>>(qkvw, qkvb, nullptr, nullptr);

    attn_kernel<<<dim3(NHEADS, NWIN_TOT), 256>>>(rb);

    gemm_kernel<1, 384, 384><<<dim3(384 / 128, MROWS / 128), 256>>>(projw, projb, x, nullptr);

    ln_kernel<false><<<MROWS, 128>>>(nullptr, n2w, n2b);

    gemm_kernel<2, 384, 1536><<<dim3(1536 / 128, MROWS / 128), 256>>>(fc1w, fc1b, nullptr, nullptr);

    gemm_kernel<3, 1536, 384><<<dim3(384 / 128, MROWS / 128), 256>>>(fc2w, fc2b, nullptr, out);
}